// round 16
// baseline (speedup 1.0000x reference)
#include <cuda_runtime.h>
#include <math_constants.h>

#define N_    256
#define D_    512
#define Q_    2048
#define C_    1000
#define IMG_  150528   // 3*224*224
#define IMG4_ 37632    // IMG_/4 = 21 * 1792
#define K_    4

// Output layout: labels | probs | images | grads (return order, float32)
#define OFF_LABELS 0
#define OFF_PROBS  (N_)
#define OFF_IMG    (N_ + N_*C_)
#define OFF_GRADS  (N_ + N_*C_ + N_*IMG_)

#define NQCH 16                 // q-chunks (128 q each)
#define NCAND (NQCH * K_)       // 64 candidates per row

// Scratch (no cudaMalloc allowed; overwritten every call => deterministic)
__device__ float4 g_bankT[128 * Q_];     // bankT[cf4][q] : 4 MB, L2-resident
__device__ float  g_binv[Q_];            // 1/max(||bank_q||, 1e-12)
__device__ float  g_finv[N_];            // 1/max(||feat_n||, 1e-12)
__device__ float  g_cv[N_ * NCAND];      // per-(row,chunk) top-4 candidate values
__device__ int    g_ci[N_ * NCAND];      // ... and their global q indices

// packed f32x2 FMA (ptxas only emits FFMA2 via explicit PTX)
__device__ __forceinline__ void ffma2(unsigned long long& acc,
                                      unsigned long long a,
                                      unsigned long long b) {
    asm("fma.rn.f32x2 %0, %1, %2, %0;" : "+l"(acc) : "l"(a), "l"(b));
}
__device__ __forceinline__ float unpack_sum(unsigned long long v) {
    float lo = __uint_as_float((unsigned)(v & 0xffffffffull));
    float hi = __uint_as_float((unsigned)(v >> 32));
    return lo + hi;
}

// ---------------------------------------------------------------------------
// Kernel 1: grid (32, 5), 512 threads.
//   by < 4 : transpose two 32x32-float4 bank tiles (4 outstanding LDGs per
//            thread before first store -> MLP=4 vs R15's 2).
//   by == 4: inverse norms. Warp w: bank rows bx*64+4w..+3; warps 0..7 also
//            do feat row bx*8+w. Deterministic (no atomics).
// ---------------------------------------------------------------------------
__global__ void __launch_bounds__(512) transpose_kernel(const float4* __restrict__ bank4,
                                                        const float4* __restrict__ feats4) {
    const int tx = threadIdx.x & 31;
    const int ty = threadIdx.x >> 5;         // 0..15

    if (blockIdx.y < 4) {
        __shared__ float4 tile[2][32][33];
        const int qt = blockIdx.x * 64;
        const int ct = blockIdx.y * 32;
        // load both tiles up-front: 4 outstanding LDG.128 per thread
        float4 v00 = bank4[(size_t)(qt + ty)      * 128 + ct + tx];
        float4 v01 = bank4[(size_t)(qt + ty + 16) * 128 + ct + tx];
        float4 v10 = bank4[(size_t)(qt + 32 + ty)      * 128 + ct + tx];
        float4 v11 = bank4[(size_t)(qt + 32 + ty + 16) * 128 + ct + tx];
        tile[0][ty][tx]      = v00;
        tile[0][ty + 16][tx] = v01;
        tile[1][ty][tx]      = v10;
        tile[1][ty + 16][tx] = v11;
        __syncthreads();
        #pragma unroll
        for (int i = 0; i < 2; i++) {
            g_bankT[(size_t)(ct + ty + 16 * i) * Q_ + qt + tx]      = tile[0][tx][ty + 16 * i];
            g_bankT[(size_t)(ct + ty + 16 * i) * Q_ + qt + 32 + tx] = tile[1][tx][ty + 16 * i];
        }
    } else {
        // norms: warp w reduces 4 bank rows; warps 0..7 also one feat row
        const int w = ty, lane = tx;
        #pragma unroll
        for (int rr = 0; rr < 4; rr++) {
            const int q = blockIdx.x * 64 + 4 * w + rr;
            float ss = 0.0f;
            #pragma unroll
            for (int c = lane; c < 128; c += 32) {
                float4 v = bank4[(size_t)q * 128 + c];
                ss += v.x * v.x + v.y * v.y + v.z * v.z + v.w * v.w;
            }
            #pragma unroll
            for (int o = 16; o > 0; o >>= 1)
                ss += __shfl_xor_sync(0xffffffffu, ss, o);
            if (lane == 0) g_binv[q] = 1.0f / fmaxf(sqrtf(ss), 1e-12f);
        }
        if (w < 8) {
            const int n = blockIdx.x * 8 + w;
            float ss = 0.0f;
            #pragma unroll
            for (int c = lane; c < 128; c += 32) {
                float4 v = feats4[(size_t)n * 128 + c];
                ss += v.x * v.x + v.y * v.y + v.z * v.z + v.w * v.w;
            }
            #pragma unroll
            for (int o = 16; o > 0; o >>= 1)
                ss += __shfl_xor_sync(0xffffffffu, ss, o);
            if (lane == 0) g_finv[n] = 1.0f / fmaxf(sqrtf(ss), 1e-12f);
        }
    }
}

// ---------------------------------------------------------------------------
// Kernel 2: dist + per-chunk top-4 (R15 champion mainloop; norm prologue
// replaced by a 16-float load of precomputed g_finv).
// Grid (16 q-chunks x 16 row-groups) = 256 blocks, 256 threads.
// Thread (h = tid>>7, ql = tid&127): rows 8h..8h+7 x q = qb + ql.
// 2 blocks/SM co-resident. Per-chunk top-4 (value desc, index asc)
// extracted in-block; no global distance matrix is ever written.
// ---------------------------------------------------------------------------
__global__ void __launch_bounds__(256) dist_kernel(const float4* __restrict__ feats4) {
    __shared__ float s_mem[16 * 512];    // 32 KB: feats tile, then 16x128 d tile
    __shared__ float s_inv[16];
    const int tid = threadIdx.x;
    const int lane = tid & 31, w = tid >> 5;
    const int h  = tid >> 7;             // row-half: 0 or 1
    const int ql = tid & 127;            // local q
    const int r0 = blockIdx.y * 16;
    const int qb = blockIdx.x * 128;

    float4* s_feat = reinterpret_cast<float4*>(s_mem);   // 16 x 128 float4
    #pragma unroll
    for (int i = tid; i < 16 * 128; i += 256)
        s_feat[i] = feats4[(size_t)r0 * 128 + i];
    if (tid < 16) s_inv[tid] = g_finv[r0 + tid];
    __syncthreads();

    unsigned long long acc[8];
    #pragma unroll
    for (int r = 0; r < 8; r++) acc[r] = 0ull;

    const ulonglong2* bT = reinterpret_cast<const ulonglong2*>(g_bankT) + qb + ql;
    const ulonglong2* sf = reinterpret_cast<const ulonglong2*>(s_mem) + (h * 8) * 128;

    #pragma unroll 4
    for (int c = 0; c < 128; c++) {
        ulonglong2 b = bT[(size_t)c * Q_];
        #pragma unroll
        for (int r = 0; r < 8; r++) {
            ulonglong2 f = sf[r * 128 + c];       // warp-broadcast LDS.128
            ffma2(acc[r], f.x, b.x);
            ffma2(acc[r], f.y, b.y);
        }
    }

    float d[8];
    const float ibn = g_binv[qb + ql];            // precomputed in transpose
    #pragma unroll
    for (int r = 0; r < 8; r++)
        d[r] = 1.0f - unpack_sum(acc[r]) * s_inv[h * 8 + r] * ibn;

    // store distance tile: s_d[rr * 128 + ql] (warp-contiguous, conflict-free)
    __syncthreads();                      // everyone done reading s_feat
    #pragma unroll
    for (int r = 0; r < 8; r++)
        s_mem[(h * 8 + r) * 128 + ql] = d[r];
    __syncthreads();

    // warp w: per-chunk top-4 of rows 2w and 2w+1 (value desc, index asc)
    #pragma unroll
    for (int rr = 2 * w; rr < 2 * w + 2; rr++) {
        float v[4];
        #pragma unroll
        for (int t = 0; t < 4; t++)
            v[t] = s_mem[rr * 128 + t * 32 + lane];   // local idx = t*32+lane

        const int out_base = ((r0 + rr) * NQCH + blockIdx.x) * K_;
        for (int k = 0; k < K_; k++) {
            float bv = -CUDART_INF_F; int bi = 1 << 30;
            #pragma unroll
            for (int t = 0; t < 4; t++) {
                if (v[t] > bv) { bv = v[t]; bi = t * 32 + lane; } // asc idx: > keeps low
            }
            #pragma unroll
            for (int o = 16; o > 0; o >>= 1) {
                float ov = __shfl_xor_sync(0xffffffffu, bv, o);
                int   oi = __shfl_xor_sync(0xffffffffu, bi, o);
                if (ov > bv || (ov == bv && oi < bi)) { bv = ov; bi = oi; }
            }
            // mask the winner locally (static indexing only)
            #pragma unroll
            for (int t = 0; t < 4; t++)
                if (bi == t * 32 + lane) v[t] = -CUDART_INF_F;
            if (lane == 0) {
                g_cv[out_base + k] = bv;
                g_ci[out_base + k] = qb + bi;
            }
        }
    }
}

// ---------------------------------------------------------------------------
// Kernel 3 (fused): grid (256, 22). Every block first re-derives the global
// top-4 for its row from the 64 per-chunk candidates (warp-0 merge, 2 cands
// per lane, ~250 cyc — free under a DRAM-bound kernel). Then:
//   blockIdx.y < 21 : image gather-mean chunk (1792 float4); n is the FAST
//                     grid dim so duplicate neighbor rows hit L2.
//   blockIdx.y == 21: probs mean + argmax label + grads mean for row n.
// ---------------------------------------------------------------------------
__global__ void fused_gather_kernel(const float4* __restrict__ img4,
                                    const float* __restrict__ bank,
                                    const float* __restrict__ probs,
                                    float* __restrict__ out) {
    const int n = blockIdx.x, tid = threadIdx.x;
    const int lane = tid & 31, w = tid >> 5;

    __shared__ int4 s_ii;
    if (w == 0) {
        // candidate indices are globally unique -> mask by index is safe
        float v0 = g_cv[n * NCAND + lane];
        float v1 = g_cv[n * NCAND + 32 + lane];
        int   c0 = g_ci[n * NCAND + lane];
        int   c1 = g_ci[n * NCAND + 32 + lane];
        int win[K_];
        for (int k = 0; k < K_; k++) {
            float bv; int bi;
            if (v0 > v1 || (v0 == v1 && c0 < c1)) { bv = v0; bi = c0; }
            else                                   { bv = v1; bi = c1; }
            #pragma unroll
            for (int o = 16; o > 0; o >>= 1) {
                float ov = __shfl_xor_sync(0xffffffffu, bv, o);
                int   oi = __shfl_xor_sync(0xffffffffu, bi, o);
                if (ov > bv || (ov == bv && oi < bi)) { bv = ov; bi = oi; }
            }
            if (c0 == bi) v0 = -CUDART_INF_F;
            if (c1 == bi) v1 = -CUDART_INF_F;
            win[k] = bi;
        }
        if (lane == 0) s_ii = make_int4(win[0], win[1], win[2], win[3]);
    }
    __syncthreads();
    const int i0 = s_ii.x, i1 = s_ii.y, i2 = s_ii.z, i3 = s_ii.w;

    if (blockIdx.y < 21) {
        const int base = blockIdx.y * 1792 + tid;
        const float4* p0 = img4 + (size_t)i0 * IMG4_;
        const float4* p1 = img4 + (size_t)i1 * IMG4_;
        const float4* p2 = img4 + (size_t)i2 * IMG4_;
        const float4* p3 = img4 + (size_t)i3 * IMG4_;
        float4* po = reinterpret_cast<float4*>(out + OFF_IMG) + (size_t)n * IMG4_;
        #pragma unroll
        for (int t = 0; t < 7; t++) {
            const int j = base + t * 256;
            float4 a = p0[j];
            float4 b = p1[j];
            float4 c = p2[j];
            float4 d = p3[j];
            float4 r;
            r.x = 0.25f * (a.x + b.x + c.x + d.x);
            r.y = 0.25f * (a.y + b.y + c.y + d.y);
            r.z = 0.25f * (a.z + b.z + c.z + d.z);
            r.w = 0.25f * (a.w + b.w + c.w + d.w);
            __stcs(po + j, r);
        }
    } else {
        // grads mean (512)
        float* outg = out + OFF_GRADS + (size_t)n * D_;
        for (int d = tid; d < D_; d += 256)
            outg[d] = 0.25f * (bank[(size_t)i0 * D_ + d] + bank[(size_t)i1 * D_ + d] +
                               bank[(size_t)i2 * D_ + d] + bank[(size_t)i3 * D_ + d]);
        // probs mean (1000) + argmax -> label
        float* outp = out + OFF_PROBS + (size_t)n * C_;
        float bv = -CUDART_INF_F; int bc = C_;
        for (int c = tid; c < C_; c += 256) {
            float p = 0.25f * (probs[(size_t)i0 * C_ + c] + probs[(size_t)i1 * C_ + c] +
                               probs[(size_t)i2 * C_ + c] + probs[(size_t)i3 * C_ + c]);
            outp[c] = p;
            if (p > bv) { bv = p; bc = c; }          // ascending c per thread
        }
        __shared__ float s_wv[8];
        __shared__ int   s_wi[8];
        #pragma unroll
        for (int o = 16; o > 0; o >>= 1) {
            float ov = __shfl_xor_sync(0xffffffffu, bv, o);
            int   oi = __shfl_xor_sync(0xffffffffu, bc, o);
            if (ov > bv || (ov == bv && oi < bc)) { bv = ov; bc = oi; }
        }
        if (lane == 0) { s_wv[w] = bv; s_wi[w] = bc; }
        __syncthreads();
        if (tid == 0) {
            float v2 = s_wv[0]; int ib = s_wi[0];
            #pragma unroll
            for (int p = 1; p < 8; p++)
                if (s_wv[p] > v2 || (s_wv[p] == v2 && s_wi[p] < ib)) {
                    v2 = s_wv[p]; ib = s_wi[p];
                }
            out[OFF_LABELS + n] = (float)ib;
        }
    }
}

// ---------------------------------------------------------------------------
extern "C" void kernel_launch(void* const* d_in, const int* in_sizes, int n_in,
                              void* d_out, int out_size) {
    const float* feats = (const float*)d_in[0];   // (256, 512)
    const float* bank  = (const float*)d_in[1];   // (2048, 512)
    const float* probs = (const float*)d_in[2];   // (2048, 1000)
    const float* img   = (const float*)d_in[3];   // (2048, 3, 224, 224)
    float* out = (float*)d_out;

    transpose_kernel<<<dim3(32, 5), 512>>>(
        reinterpret_cast<const float4*>(bank),
        reinterpret_cast<const float4*>(feats));
    dist_kernel<<<dim3(NQCH, 16), 256>>>(
        reinterpret_cast<const float4*>(feats));
    fused_gather_kernel<<<dim3(N_, 22), 256>>>(
        reinterpret_cast<const float4*>(img), bank, probs, out);
}